// round 8
// baseline (speedup 1.0000x reference)
#include <cuda_runtime.h>
#include <cuda_bf16.h>
#include <math_constants.h>
#include <cstdint>

#define B_   4
#define S_   2048
#define D_   256
#define H_   8
#define HD_  32
#define KEEP 204            // int(2048 * 0.1)
#define KPAD 208            // padded keys (13 x 16)
#define ROWS (B_ * S_)      // 8192
#define KV_ROWS (B_ * KEEP) // 816
#define KD   256

// ------------------------- scratch (static device globals) -------------------
__device__ float g_importance[ROWS];
__device__ int   g_rowmap[KV_ROWS];
__device__ __nv_bfloat16 g_xhi[ROWS * D_],   g_xlo[ROWS * D_];
__device__ __nv_bfloat16 g_winhi[3 * D_ * D_], g_winlo[3 * D_ * D_];
__device__ __nv_bfloat16 g_wouthi[D_ * D_],  g_woutlo[D_ * D_];
__device__ __nv_bfloat16 g_qhi[ROWS * D_],   g_qlo[ROWS * D_];      // Q * log2e/sqrt(hd)
__device__ __nv_bfloat16 g_khi[KV_ROWS * D_], g_klo[KV_ROWS * D_];
__device__ __nv_bfloat16 g_vthi[B_ * H_ * HD_ * KPAD], g_vtlo[B_ * H_ * HD_ * KPAD];
__device__ __nv_bfloat16 g_athi[ROWS * D_],  g_atlo[ROWS * D_];

// ========================= helpers ============================================
__device__ __forceinline__ uint32_t smem_u32(const void* p) {
    uint32_t a;
    asm("{ .reg .u64 t; cvta.to.shared.u64 t, %1; cvt.u32.u64 %0, t; }" : "=r"(a) : "l"(p));
    return a;
}
__device__ __forceinline__ void ldsm_x4(uint32_t& r0, uint32_t& r1, uint32_t& r2,
                                        uint32_t& r3, uint32_t addr) {
    asm volatile("ldmatrix.sync.aligned.m8n8.x4.shared.b16 {%0,%1,%2,%3}, [%4];"
                 : "=r"(r0), "=r"(r1), "=r"(r2), "=r"(r3) : "r"(addr));
}
__device__ __forceinline__ void mma_bf16(float* c, const uint32_t* a, const uint32_t* b) {
    asm volatile("mma.sync.aligned.m16n8k16.row.col.f32.bf16.bf16.f32 "
                 "{%0,%1,%2,%3}, {%4,%5,%6,%7}, {%8,%9}, {%0,%1,%2,%3};"
                 : "+f"(c[0]), "+f"(c[1]), "+f"(c[2]), "+f"(c[3])
                 : "r"(a[0]), "r"(a[1]), "r"(a[2]), "r"(a[3]), "r"(b[0]), "r"(b[1]));
}
#define CP16(dst, src) \
    asm volatile("cp.async.cg.shared.global [%0], [%1], 16;" :: "r"(dst), "l"(src))
#define CP_COMMIT() asm volatile("cp.async.commit_group;" ::: "memory")
#define CP_WAIT(n)  asm volatile("cp.async.wait_group %0;" :: "n"(n) : "memory")

__device__ __forceinline__ void split_bf16(float v, __nv_bfloat16& h, __nv_bfloat16& l) {
    h = __float2bfloat16(v);
    l = __float2bfloat16(v - __bfloat162float(h));
}
__device__ __forceinline__ void pack_hi_lo(float a, float b, uint32_t& hi, uint32_t& lo) {
    __nv_bfloat16 ha, la, hb, lb;
    split_bf16(a, ha, la); split_bf16(b, hb, lb);
    __nv_bfloat162 th = __halves2bfloat162(ha, hb);
    __nv_bfloat162 tl = __halves2bfloat162(la, lb);
    hi = *(uint32_t*)&th; lo = *(uint32_t*)&tl;
}
// 2^x via FMA pipe (no MUFU): magic rounding + degree-5 poly, rel err < 3e-6
__device__ __forceinline__ float exp2_fast(float x) {
    x = fmaxf(x, -120.f);
    float t = x + 12582912.f;
    float f = x - (t - 12582912.f);
    uint32_t ti = __float_as_uint(t);
    float s = __uint_as_float((ti << 23) + 0x3F800000u);
    float p = 1.33335581e-3f;
    p = fmaf(p, f, 9.61812911e-3f);
    p = fmaf(p, f, 5.55041087e-2f);
    p = fmaf(p, f, 2.40226507e-1f);
    p = fmaf(p, f, 6.93147181e-1f);
    p = fmaf(p, f, 1.0f);
    return p * s;
}

// ------------------------- merged fp32 -> bf16 hi/lo split --------------------
#define CN1 (ROWS * D_ / 4)
#define CN2 (3 * D_ * D_ / 4)
#define CN3 (D_ * D_ / 4)
__global__ void convert_all(const float4* __restrict__ x,
                            const float4* __restrict__ w_in,
                            const float4* __restrict__ w_out) {
    int i = blockIdx.x * blockDim.x + threadIdx.x;
    const float4* src;
    __nv_bfloat162 *hi, *lo;
    int off;
    if (i < CN1) {
        src = x; hi = (__nv_bfloat162*)g_xhi; lo = (__nv_bfloat162*)g_xlo; off = i;
    } else if (i < CN1 + CN2) {
        src = w_in; hi = (__nv_bfloat162*)g_winhi; lo = (__nv_bfloat162*)g_winlo; off = i - CN1;
    } else if (i < CN1 + CN2 + CN3) {
        src = w_out; hi = (__nv_bfloat162*)g_wouthi; lo = (__nv_bfloat162*)g_woutlo;
        off = i - CN1 - CN2;
    } else return;
    float4 v = src[off];
    __nv_bfloat16 hx, hy, hz, hw, lx, ly, lz, lw;
    split_bf16(v.x, hx, lx); split_bf16(v.y, hy, ly);
    split_bf16(v.z, hz, lz); split_bf16(v.w, hw, lw);
    hi[2*off]   = __halves2bfloat162(hx, hy);
    hi[2*off+1] = __halves2bfloat162(hz, hw);
    lo[2*off]   = __halves2bfloat162(lx, ly);
    lo[2*off+1] = __halves2bfloat162(lz, lw);
}

// ========================= pipelined bf16x3 GEMM ==============================
#define GKP 80
#define ST_A_HI 0
#define ST_A_LO 10240
#define ST_B_HI 20480
#define ST_B_LO 30720
#define ST_SIZE 40960
#define SMEM_GM (2 * ST_SIZE)

__global__ __launch_bounds__(256) void gemm_bf16(
    const __nv_bfloat16* __restrict__ Ahi, const __nv_bfloat16* __restrict__ Alo,
    const int* __restrict__ rowmap,
    const __nv_bfloat16* __restrict__ Bhi, const __nv_bfloat16* __restrict__ Blo,
    const float* __restrict__ bias, int M, int N, int mode, float scale,
    float* __restrict__ Cf, __nv_bfloat16* __restrict__ Chi, __nv_bfloat16* __restrict__ Clo,
    __nv_bfloat16* __restrict__ VThi, __nv_bfloat16* __restrict__ VTlo) {
    extern __shared__ char smem[];
    uint32_t sb = smem_u32(smem);
    int tid = threadIdx.x, wid = tid >> 5, lane = tid & 31;
    int rowBase = blockIdx.y * 128, colBase = blockIdx.x * 128;
    int warp_m = (wid >> 2) * 64;
    int warp_n = (wid & 3) * 32;

    int id0 = tid * 2, id1 = id0 + 1;
    int r0 = id0 >> 2, c0 = id0 & 3;
    int r1 = id1 >> 2, c1 = id1 & 3;
    int ga0 = (rowBase + r0 < M) ? (rowmap ? rowmap[rowBase + r0] : rowBase + r0) : 0;
    int ga1 = (rowBase + r1 < M) ? (rowmap ? rowmap[rowBase + r1] : rowBase + r1) : 0;
    const __nv_bfloat16* sAh0 = Ahi + (size_t)ga0 * KD + c0 * 8;
    const __nv_bfloat16* sAh1 = Ahi + (size_t)ga1 * KD + c1 * 8;
    const __nv_bfloat16* sAl0 = Alo + (size_t)ga0 * KD + c0 * 8;
    const __nv_bfloat16* sAl1 = Alo + (size_t)ga1 * KD + c1 * 8;
    const __nv_bfloat16* sBh0 = Bhi + (size_t)(colBase + r0) * KD + c0 * 8;
    const __nv_bfloat16* sBh1 = Bhi + (size_t)(colBase + r1) * KD + c1 * 8;
    const __nv_bfloat16* sBl0 = Blo + (size_t)(colBase + r0) * KD + c0 * 8;
    const __nv_bfloat16* sBl1 = Blo + (size_t)(colBase + r1) * KD + c1 * 8;
    uint32_t d0 = sb + (uint32_t)(r0 * GKP + c0 * 16);
    uint32_t d1 = sb + (uint32_t)(r1 * GKP + c1 * 16);

    auto issue = [&](int kt, int st) {
        uint32_t so = (uint32_t)st * ST_SIZE;
        int ko = kt * 32;
        CP16(d0 + so + ST_A_HI, sAh0 + ko);  CP16(d1 + so + ST_A_HI, sAh1 + ko);
        CP16(d0 + so + ST_A_LO, sAl0 + ko);  CP16(d1 + so + ST_A_LO, sAl1 + ko);
        CP16(d0 + so + ST_B_HI, sBh0 + ko);  CP16(d1 + so + ST_B_HI, sBh1 + ko);
        CP16(d0 + so + ST_B_LO, sBl0 + ko);  CP16(d1 + so + ST_B_LO, sBl1 + ko);
        CP_COMMIT();
    };

    uint32_t arel[4];
    #pragma unroll
    for (int mf = 0; mf < 4; mf++)
        arel[mf] = (uint32_t)((warp_m + mf * 16 + (lane & 15)) * GKP + (lane >> 4) * 16);
    int bg = lane >> 3, br = lane & 7;
    uint32_t brel0 = (uint32_t)((warp_n + (bg >> 1) * 8 + br) * GKP + (bg & 1) * 16);
    uint32_t brel1 = brel0 + 16 * GKP;

    float acc[4][4][4] = {};

    issue(0, 0);
    #pragma unroll 1
    for (int kt = 0; kt < 8; kt++) {
        int st = kt & 1;
        if (kt + 1 < 8) { issue(kt + 1, (kt + 1) & 1); CP_WAIT(1); }
        else            { CP_WAIT(0); }
        __syncthreads();
        uint32_t base = sb + (uint32_t)st * ST_SIZE;
        #pragma unroll
        for (int kc = 0; kc < 2; kc++) {
            uint32_t koff = (uint32_t)kc * 32;
            uint32_t bh[4][2], bl[4][2];
            ldsm_x4(bh[0][0], bh[0][1], bh[1][0], bh[1][1], base + ST_B_HI + brel0 + koff);
            ldsm_x4(bh[2][0], bh[2][1], bh[3][0], bh[3][1], base + ST_B_HI + brel1 + koff);
            ldsm_x4(bl[0][0], bl[0][1], bl[1][0], bl[1][1], base + ST_B_LO + brel0 + koff);
            ldsm_x4(bl[2][0], bl[2][1], bl[3][0], bl[3][1], base + ST_B_LO + brel1 + koff);
            #pragma unroll
            for (int mf = 0; mf < 4; mf++) {
                uint32_t ah[4], al[4];
                ldsm_x4(ah[0], ah[1], ah[2], ah[3], base + ST_A_HI + arel[mf] + koff);
                ldsm_x4(al[0], al[1], al[2], al[3], base + ST_A_LO + arel[mf] + koff);
                #pragma unroll
                for (int nf = 0; nf < 4; nf++) {
                    mma_bf16(acc[mf][nf], ah, bh[nf]);
                    mma_bf16(acc[mf][nf], ah, bl[nf]);
                    mma_bf16(acc[mf][nf], al, bh[nf]);
                }
            }
        }
        __syncthreads();
    }

    #pragma unroll
    for (int mf = 0; mf < 4; mf++) {
        #pragma unroll
        for (int nf = 0; nf < 4; nf++) {
            int n = colBase + warp_n + nf * 8 + (lane & 3) * 2;
            float b0 = __ldg(bias + n), b1 = __ldg(bias + n + 1);
            #pragma unroll
            for (int half = 0; half < 2; half++) {
                int m = rowBase + warp_m + mf * 16 + (lane >> 2) + half * 8;
                if (m >= M) continue;
                float o0 = acc[mf][nf][half * 2 + 0] + b0;
                float o1 = acc[mf][nf][half * 2 + 1] + b1;
                if (mode == 0) {
                    *(float2*)(Cf + (size_t)m * N + n) = make_float2(o0, o1);
                } else if (mode == 1) {
                    o0 *= scale; o1 *= scale;
                    __nv_bfloat16 h0, l0, h1, l1;
                    split_bf16(o0, h0, l0); split_bf16(o1, h1, l1);
                    *(__nv_bfloat162*)(Chi + (size_t)m * N + n) = __halves2bfloat162(h0, h1);
                    *(__nv_bfloat162*)(Clo + (size_t)m * N + n) = __halves2bfloat162(l0, l1);
                } else {
                    __nv_bfloat16 h0, l0, h1, l1;
                    split_bf16(o0, h0, l0); split_bf16(o1, h1, l1);
                    if (n < 256) {
                        *(__nv_bfloat162*)(Chi + (size_t)m * 256 + n) = __halves2bfloat162(h0, h1);
                        *(__nv_bfloat162*)(Clo + (size_t)m * 256 + n) = __halves2bfloat162(l0, l1);
                    } else {
                        int bb = m / KEEP, j = m - bb * KEEP;
                        int hh = (n - 256) >> 5, dd = (n - 256) & 31;
                        size_t i0 = ((size_t)(bb * H_ + hh) * HD_ + dd) * KPAD + j;
                        size_t i1 = ((size_t)(bb * H_ + hh) * HD_ + dd + 1) * KPAD + j;
                        VThi[i0] = h0; VTlo[i0] = l0;
                        VThi[i1] = h1; VTlo[i1] = l1;
                    }
                }
            }
        }
    }
}

// ========================= MMA attention (register softmax) ==================
#define AQS 80
#define PVS 432
#define A_KHI  0
#define A_KLO  (A_KHI + KPAD * AQS)
#define A_QHI  (A_KLO + KPAD * AQS)
#define A_QLO  (A_QHI + 64 * AQS)
#define A_VTHI (A_QLO + 64 * AQS)
#define A_VTLO (A_VTHI + HD_ * PVS)
#define SMEM_AT (A_VTLO + HD_ * PVS)      // 71168

__global__ __launch_bounds__(128) void attn_mma() {
    extern __shared__ char smem[];
    uint32_t sb = smem_u32(smem);
    int tid = threadIdx.x, wid = tid >> 5, lane = tid & 31;
    int bh_ = blockIdx.x;
    int b = bh_ >> 3, h = bh_ & 7;
    int qbase = blockIdx.y * 64;

    for (int i = tid; i < KPAD * 4; i += 128) {
        int j = i >> 2, c = i & 3;
        uint4 vh = make_uint4(0, 0, 0, 0), vl = vh;
        if (j < KEEP) {
            size_t off = (size_t)(b * KEEP + j) * D_ + h * HD_ + c * 8;
            vh = *(const uint4*)(g_khi + off);
            vl = *(const uint4*)(g_klo + off);
        }
        *(uint4*)(smem + A_KHI + j * AQS + c * 16) = vh;
        *(uint4*)(smem + A_KLO + j * AQS + c * 16) = vl;
    }
    for (int i = tid; i < 64 * 4; i += 128) {
        int r = i >> 2, c = i & 3;
        size_t off = (size_t)(b * S_ + qbase + r) * D_ + h * HD_ + c * 8;
        *(uint4*)(smem + A_QHI + r * AQS + c * 16) = *(const uint4*)(g_qhi + off);
        *(uint4*)(smem + A_QLO + r * AQS + c * 16) = *(const uint4*)(g_qlo + off);
    }
    for (int i = tid; i < HD_ * 26; i += 128) {
        int d = i / 26, c = i % 26;
        size_t off = ((size_t)(b * H_ + h) * HD_ + d) * KPAD + c * 8;
        if (c < 25) {
            *(uint4*)(smem + A_VTHI + d * PVS + c * 16) = *(const uint4*)(g_vthi + off);
            *(uint4*)(smem + A_VTLO + d * PVS + c * 16) = *(const uint4*)(g_vtlo + off);
        } else {
            uint2 vh = *(const uint2*)(g_vthi + off);
            uint2 vl = *(const uint2*)(g_vtlo + off);
            *(uint4*)(smem + A_VTHI + d * PVS + c * 16) = make_uint4(vh.x, vh.y, 0, 0);
            *(uint4*)(smem + A_VTLO + d * PVS + c * 16) = make_uint4(vl.x, vl.y, 0, 0);
        }
    }
    __syncthreads();

    int warp_m = wid * 16;
    int bg = lane >> 3, br = lane & 7;

    uint32_t aqh[2][4], aql[2][4];
    {
        uint32_t ar = (uint32_t)((warp_m + (lane & 15)) * AQS + (lane >> 4) * 16);
        #pragma unroll
        for (int ks = 0; ks < 2; ks++) {
            ldsm_x4(aqh[ks][0], aqh[ks][1], aqh[ks][2], aqh[ks][3], sb + A_QHI + ar + ks * 32);
            ldsm_x4(aql[ks][0], aql[ks][1], aql[ks][2], aql[ks][3], sb + A_QLO + ar + ks * 32);
        }
    }
    float sacc[26][4];
    #pragma unroll
    for (int t = 0; t < 26; t++)
        #pragma unroll
        for (int j = 0; j < 4; j++) sacc[t][j] = 0.f;

    #pragma unroll
    for (int nc = 0; nc < 13; nc++) {
        uint32_t brel = (uint32_t)((nc * 16 + (bg >> 1) * 8 + br) * AQS + (bg & 1) * 16);
        #pragma unroll
        for (int ks = 0; ks < 2; ks++) {
            uint32_t bh[2][2], bl[2][2];
            ldsm_x4(bh[0][0], bh[0][1], bh[1][0], bh[1][1], sb + A_KHI + brel + ks * 32);
            ldsm_x4(bl[0][0], bl[0][1], bl[1][0], bl[1][1], sb + A_KLO + brel + ks * 32);
            #pragma unroll
            for (int nf = 0; nf < 2; nf++) {
                mma_bf16(sacc[nc * 2 + nf], aqh[ks], bh[nf]);
                mma_bf16(sacc[nc * 2 + nf], aql[ks], bh[nf]);
                mma_bf16(sacc[nc * 2 + nf], aqh[ks], bl[nf]);
            }
        }
    }

    if ((lane & 3) >= 2) {
        sacc[25][0] = -1e30f; sacc[25][1] = -1e30f;
        sacc[25][2] = -1e30f; sacc[25][3] = -1e30f;
    }

    float mx0 = -1e30f, mx1 = -1e30f;
    #pragma unroll
    for (int t = 0; t < 26; t++) {
        mx0 = fmaxf(mx0, fmaxf(sacc[t][0], sacc[t][1]));
        mx1 = fmaxf(mx1, fmaxf(sacc[t][2], sacc[t][3]));
    }
    mx0 = fmaxf(mx0, __shfl_xor_sync(0xffffffffu, mx0, 1));
    mx0 = fmaxf(mx0, __shfl_xor_sync(0xffffffffu, mx0, 2));
    mx1 = fmaxf(mx1, __shfl_xor_sync(0xffffffffu, mx1, 1));
    mx1 = fmaxf(mx1, __shfl_xor_sync(0xffffffffu, mx1, 2));
    float sum0 = 0.f, sum1 = 0.f;
    #pragma unroll
    for (int t = 0; t < 26; t++) {
        sacc[t][0] = exp2_fast(sacc[t][0] - mx0); sum0 += sacc[t][0];
        sacc[t][1] = exp2_fast(sacc[t][1] - mx0); sum0 += sacc[t][1];
        sacc[t][2] = exp2_fast(sacc[t][2] - mx1); sum1 += sacc[t][2];
        sacc[t][3] = exp2_fast(sacc[t][3] - mx1); sum1 += sacc[t][3];
    }
    sum0 += __shfl_xor_sync(0xffffffffu, sum0, 1);
    sum0 += __shfl_xor_sync(0xffffffffu, sum0, 2);
    sum1 += __shfl_xor_sync(0xffffffffu, sum1, 1);
    sum1 += __shfl_xor_sync(0xffffffffu, sum1, 2);
    float inv0 = 1.f / sum0, inv1 = 1.f / sum1;

    float oacc[4][4] = {};
    uint32_t br0 = (uint32_t)(((bg >> 1) * 8 + br) * PVS + (bg & 1) * 16);
    uint32_t br1 = br0 + 16 * PVS;
    #pragma unroll
    for (int ks = 0; ks < 13; ks++) {
        uint32_t ph[4], pl[4];
        pack_hi_lo(sacc[2*ks][0],   sacc[2*ks][1],   ph[0], pl[0]);
        pack_hi_lo(sacc[2*ks][2],   sacc[2*ks][3],   ph[1], pl[1]);
        pack_hi_lo(sacc[2*ks+1][0], sacc[2*ks+1][1], ph[2], pl[2]);
        pack_hi_lo(sacc[2*ks+1][2], sacc[2*ks+1][3], ph[3], pl[3]);
        uint32_t koff = (uint32_t)ks * 32;
        uint32_t vh[4][2], vl[4][2];
        ldsm_x4(vh[0][0], vh[0][1], vh[1][0], vh[1][1], sb + A_VTHI + br0 + koff);
        ldsm_x4(vh[2][0], vh[2][1], vh[3][0], vh[3][1], sb + A_VTHI + br1 + koff);
        ldsm_x4(vl[0][0], vl[0][1], vl[1][0], vl[1][1], sb + A_VTLO + br0 + koff);
        ldsm_x4(vl[2][0], vl[2][1], vl[3][0], vl[3][1], sb + A_VTLO + br1 + koff);
        #pragma unroll
        for (int nf = 0; nf < 4; nf++) {
            mma_bf16(oacc[nf], ph, vh[nf]);
            mma_bf16(oacc[nf], pl, vh[nf]);
            mma_bf16(oacc[nf], ph, vl[nf]);
        }
    }

    #pragma unroll
    for (int nf = 0; nf < 4; nf++) {
        int col = h * HD_ + nf * 8 + (lane & 3) * 2;
        #pragma unroll
        for (int half = 0; half < 2; half++) {
            int row = warp_m + (lane >> 2) + half * 8;
            float il = half ? inv1 : inv0;
            float o0 = oacc[nf][half * 2 + 0] * il;
            float o1 = oacc[nf][half * 2 + 1] * il;
            __nv_bfloat16 h0, l0, h1, l1;
            split_bf16(o0, h0, l0); split_bf16(o1, h1, l1);
            size_t m = (size_t)(b * S_ + qbase + row) * D_ + col;
            *(__nv_bfloat162*)(g_athi + m) = __halves2bfloat162(h0, h1);
            *(__nv_bfloat162*)(g_atlo + m) = __halves2bfloat162(l0, l1);
        }
    }
}

// ------------------------- gate GEMM + fused relu/dot/sigmoid ----------------
__global__ __launch_bounds__(256) void gate_gemm(
    const float* __restrict__ A, const float* __restrict__ W,
    const float* __restrict__ bias,
    const float* __restrict__ w2, const float* __restrict__ b2) {
    __shared__ float As[16][68];
    __shared__ float Ws[16][68];
    int tid = threadIdx.x;
    int rowBase = blockIdx.x * 64;
    int ar = tid & 63, ac = (tid >> 6) * 4;
    const float* asrc = A + (size_t)(rowBase + ar) * KD + ac;
    const float* wsrc = W + (size_t)ar * KD + ac;
    float4 a0 = *(const float4*)asrc;
    float4 w0 = *(const float4*)wsrc;
    int tx = tid & 15, ty = tid >> 4;
    float acc[4][4] = {};
    for (int k0 = 0; k0 < KD; k0 += 16) {
        As[ac+0][ar]=a0.x; As[ac+1][ar]=a0.y; As[ac+2][ar]=a0.z; As[ac+3][ar]=a0.w;
        Ws[ac+0][ar]=w0.x; Ws[ac+1][ar]=w0.y; Ws[ac+2][ar]=w0.z; Ws[ac+3][ar]=w0.w;
        __syncthreads();
        if (k0 + 16 < KD) {
            a0 = *(const float4*)(asrc + k0 + 16);
            w0 = *(const float4*)(wsrc + k0 + 16);
        }
        #pragma unroll
        for (int kk = 0; kk < 16; kk++) {
            float a[4], w[4];
            *(float4*)a = *(const float4*)&As[kk][ty * 4];
            *(float4*)w = *(const float4*)&Ws[kk][tx * 4];
            #pragma unroll
            for (int i = 0; i < 4; i++)
                #pragma unroll
                for (int j = 0; j < 4; j++)
                    acc[i][j] = fmaf(a[i], w[j], acc[i][j]);
        }
        __syncthreads();
    }
    // fused: relu -> dot(w2) -> reduce over 16 col-threads -> sigmoid
    float b1v[4], w2v[4];
    #pragma unroll
    for (int j = 0; j < 4; j++) {
        b1v[j] = bias[tx * 4 + j];
        w2v[j] = w2[tx * 4 + j];
    }
    float bb2 = b2[0];
    #pragma unroll
    for (int i = 0; i < 4; i++) {
        float part = 0.f;
        #pragma unroll
        for (int j = 0; j < 4; j++)
            part += fmaxf(acc[i][j] + b1v[j], 0.f) * w2v[j];
        part += __shfl_xor_sync(0xffffffffu, part, 1);
        part += __shfl_xor_sync(0xffffffffu, part, 2);
        part += __shfl_xor_sync(0xffffffffu, part, 4);
        part += __shfl_xor_sync(0xffffffffu, part, 8);
        if (tx == 0)
            g_importance[rowBase + ty * 4 + i] = 1.f / (1.f + expf(-(part + bb2)));
    }
}

// ------------------------- radix-select top-k ---------------------------------
// One block per batch, 256 threads. Sigmoid output > 0 => fp32 bits monotonic.
__global__ __launch_bounds__(256) void topk_radix() {
    __shared__ uint32_t bits[S_];
    __shared__ int hist[256];
    __shared__ int s_bin, s_acc;
    __shared__ int cnt_gt, eqn;
    __shared__ int eqlist[256];
    int b = blockIdx.x, t = threadIdx.x;
    for (int i = t; i < S_; i += 256)
        bits[i] = __float_as_uint(g_importance[b * S_ + i]);
    __syncthreads();

    uint32_t prefix = 0, prefmask = 0;
    int k_rem = KEEP;
    #pragma unroll
    for (int lev = 0; lev < 4; lev++) {
        int shift = 24 - lev * 8;
        if (t < 256) hist[t] = 0;
        __syncthreads();
        for (int i = t; i < S_; i += 256) {
            uint32_t v = bits[i];
            if ((v & prefmask) == prefix) atomicAdd(&hist[(v >> shift) & 255], 1);
        }
        __syncthreads();
        if (t == 0) {
            int acc = 0, bin = 255;
            for (; bin > 0; bin--) {
                if (acc + hist[bin] >= k_rem) break;
                acc += hist[bin];
            }
            s_bin = bin; s_acc = acc;
        }
        __syncthreads();
        prefix |= ((uint32_t)s_bin) << shift;
        prefmask |= (0xFFu << shift);
        k_rem -= s_acc;
        __syncthreads();
    }
    // prefix == exact threshold T. Keep all > T; take k_rem lowest-index == T.
    if (t == 0) { cnt_gt = 0; eqn = 0; }
    __syncthreads();
    for (int i = t; i < S_; i += 256) {
        uint32_t v = bits[i];
        if (v > prefix) {
            int s = atomicAdd(&cnt_gt, 1);
            g_rowmap[b * KEEP + s] = b * S_ + i;
        } else if (v == prefix) {
            int s = atomicAdd(&eqn, 1);
            if (s < 256) eqlist[s] = i;
        }
    }
    __syncthreads();
    int ne = min(eqn, 256);
    if (t < ne) {
        int idx = eqlist[t], rank = 0;
        for (int j = 0; j < ne; j++) rank += (eqlist[j] < idx);
        if (rank < k_rem) g_rowmap[b * KEEP + cnt_gt + rank] = b * S_ + idx;
    }
}

// ------------------------- host launch ---------------------------------------
extern "C" void kernel_launch(void* const* d_in, const int* in_sizes, int n_in,
                              void* d_out, int out_size) {
    const float* x       = (const float*)d_in[0];
    const float* w_in    = (const float*)d_in[1];
    const float* b_in    = (const float*)d_in[2];
    const float* w_out   = (const float*)d_in[3];
    const float* b_out   = (const float*)d_in[4];
    const float* gate_w1 = (const float*)d_in[5];
    const float* gate_b1 = (const float*)d_in[6];
    const float* gate_w2 = (const float*)d_in[7];
    const float* gate_b2 = (const float*)d_in[8];
    float* out = (float*)d_out;

    void *pRowmap;
    void *pXhi, *pXlo, *pWinhi, *pWinlo, *pWouthi, *pWoutlo;
    void *pQhi, *pQlo, *pKhi, *pKlo, *pVthi, *pVtlo, *pAthi, *pAtlo;
    cudaGetSymbolAddress(&pRowmap, g_rowmap);
    cudaGetSymbolAddress(&pXhi, g_xhi);     cudaGetSymbolAddress(&pXlo, g_xlo);
    cudaGetSymbolAddress(&pWinhi, g_winhi); cudaGetSymbolAddress(&pWinlo, g_winlo);
    cudaGetSymbolAddress(&pWouthi, g_wouthi); cudaGetSymbolAddress(&pWoutlo, g_woutlo);
    cudaGetSymbolAddress(&pQhi, g_qhi);     cudaGetSymbolAddress(&pQlo, g_qlo);
    cudaGetSymbolAddress(&pKhi, g_khi);     cudaGetSymbolAddress(&pKlo, g_klo);
    cudaGetSymbolAddress(&pVthi, g_vthi);   cudaGetSymbolAddress(&pVtlo, g_vtlo);
    cudaGetSymbolAddress(&pAthi, g_athi);   cudaGetSymbolAddress(&pAtlo, g_atlo);

    cudaFuncSetAttribute(gemm_bf16, cudaFuncAttributeMaxDynamicSharedMemorySize, SMEM_GM);
    cudaFuncSetAttribute(attn_mma, cudaFuncAttributeMaxDynamicSharedMemorySize, SMEM_AT);

    // 1. gate (exact fp32, fused relu/dot/sigmoid) -> importance
    gate_gemm<<<ROWS / 64, 256>>>(x, gate_w1, gate_b1, gate_w2, gate_b2);

    // 2. radix-select top-k -> rowmap
    topk_radix<<<B_, 256>>>();

    // 3. merged operand splits
    convert_all<<<(CN1 + CN2 + CN3 + 255) / 256, 256>>>(
        (const float4*)x, (const float4*)w_in, (const float4*)w_out);

    // scale = log2(e) / sqrt(32): scores in log2 domain
    const float scale = 1.4426950408889634f * 0.17677669529663687f;

    // 4. Q = (x @ Wq^T + bq) * scale -> bf16 hi/lo
    gemm_bf16<<<dim3(D_ / 128, ROWS / 128), 256, SMEM_GM>>>(
        (const __nv_bfloat16*)pXhi, (const __nv_bfloat16*)pXlo, nullptr,
        (const __nv_bfloat16*)pWinhi, (const __nv_bfloat16*)pWinlo,
        b_in, ROWS, D_, 1, scale,
        nullptr, (__nv_bfloat16*)pQhi, (__nv_bfloat16*)pQlo, nullptr, nullptr);

    // 5. K,V at kept rows -> K rows + V^T, bf16 hi/lo
    gemm_bf16<<<dim3((2 * D_) / 128, (KV_ROWS + 127) / 128), 256, SMEM_GM>>>(
        (const __nv_bfloat16*)pXhi, (const __nv_bfloat16*)pXlo, (const int*)pRowmap,
        (const __nv_bfloat16*)pWinhi + D_ * D_, (const __nv_bfloat16*)pWinlo + D_ * D_,
        b_in + D_, KV_ROWS, 2 * D_, 2, 1.f,
        nullptr, (__nv_bfloat16*)pKhi, (__nv_bfloat16*)pKlo,
        (__nv_bfloat16*)pVthi, (__nv_bfloat16*)pVtlo);

    // 6. attention (register softmax, FMA-pipe exp)
    attn_mma<<<dim3(B_ * H_, S_ / 64), 128, SMEM_AT>>>();

    // 7. out projection (fp32 out)
    gemm_bf16<<<dim3(D_ / 128, ROWS / 128), 256, SMEM_GM>>>(
        (const __nv_bfloat16*)pAthi, (const __nv_bfloat16*)pAtlo, nullptr,
        (const __nv_bfloat16*)pWouthi, (const __nv_bfloat16*)pWoutlo,
        b_out, ROWS, D_, 0, 1.f,
        out, nullptr, nullptr, nullptr, nullptr);
}

// round 9
// speedup vs baseline: 1.1234x; 1.1234x over previous
#include <cuda_runtime.h>
#include <cuda_bf16.h>
#include <math_constants.h>
#include <cstdint>

#define B_   4
#define S_   2048
#define D_   256
#define H_   8
#define HD_  32
#define KEEP 204            // int(2048 * 0.1)
#define KPAD 208            // padded keys (13 x 16)
#define ROWS (B_ * S_)      // 8192
#define KV_ROWS (B_ * KEEP) // 816
#define KD   256

// ------------------------- scratch (static device globals) -------------------
__device__ float g_importance[ROWS];
__device__ int   g_rowmap[KV_ROWS];
__device__ __nv_bfloat16 g_xhi[ROWS * D_],   g_xlo[ROWS * D_];
__device__ __nv_bfloat16 g_winhi[3 * D_ * D_], g_winlo[3 * D_ * D_];
__device__ __nv_bfloat16 g_wouthi[D_ * D_],  g_woutlo[D_ * D_];
__device__ __nv_bfloat16 g_qhi[ROWS * D_],   g_qlo[ROWS * D_];      // Q * log2e/sqrt(hd)
__device__ __nv_bfloat16 g_khi[KV_ROWS * D_], g_klo[KV_ROWS * D_];
__device__ __nv_bfloat16 g_vthi[B_ * H_ * HD_ * KPAD], g_vtlo[B_ * H_ * HD_ * KPAD];
__device__ __nv_bfloat16 g_athi[ROWS * D_],  g_atlo[ROWS * D_];

// ========================= helpers ============================================
__device__ __forceinline__ uint32_t smem_u32(const void* p) {
    uint32_t a;
    asm("{ .reg .u64 t; cvta.to.shared.u64 t, %1; cvt.u32.u64 %0, t; }" : "=r"(a) : "l"(p));
    return a;
}
__device__ __forceinline__ void ldsm_x4(uint32_t& r0, uint32_t& r1, uint32_t& r2,
                                        uint32_t& r3, uint32_t addr) {
    asm volatile("ldmatrix.sync.aligned.m8n8.x4.shared.b16 {%0,%1,%2,%3}, [%4];"
                 : "=r"(r0), "=r"(r1), "=r"(r2), "=r"(r3) : "r"(addr));
}
__device__ __forceinline__ void mma_bf16(float* c, const uint32_t* a, const uint32_t* b) {
    asm volatile("mma.sync.aligned.m16n8k16.row.col.f32.bf16.bf16.f32 "
                 "{%0,%1,%2,%3}, {%4,%5,%6,%7}, {%8,%9}, {%0,%1,%2,%3};"
                 : "+f"(c[0]), "+f"(c[1]), "+f"(c[2]), "+f"(c[3])
                 : "r"(a[0]), "r"(a[1]), "r"(a[2]), "r"(a[3]), "r"(b[0]), "r"(b[1]));
}
#define CP16(dst, src) \
    asm volatile("cp.async.cg.shared.global [%0], [%1], 16;" :: "r"(dst), "l"(src))
#define CP_COMMIT() asm volatile("cp.async.commit_group;" ::: "memory")
#define CP_WAIT(n)  asm volatile("cp.async.wait_group %0;" :: "n"(n) : "memory")

__device__ __forceinline__ void split_bf16(float v, __nv_bfloat16& h, __nv_bfloat16& l) {
    h = __float2bfloat16(v);
    l = __float2bfloat16(v - __bfloat162float(h));
}
__device__ __forceinline__ void pack_hi_lo(float a, float b, uint32_t& hi, uint32_t& lo) {
    __nv_bfloat16 ha, la, hb, lb;
    split_bf16(a, ha, la); split_bf16(b, hb, lb);
    __nv_bfloat162 th = __halves2bfloat162(ha, hb);
    __nv_bfloat162 tl = __halves2bfloat162(la, lb);
    hi = *(uint32_t*)&th; lo = *(uint32_t*)&tl;
}
// 2^x via FMA pipe (no MUFU): magic rounding + degree-5 poly, rel err < 3e-6
__device__ __forceinline__ float exp2_fast(float x) {
    x = fmaxf(x, -120.f);
    float t = x + 12582912.f;
    float f = x - (t - 12582912.f);
    uint32_t ti = __float_as_uint(t);
    float s = __uint_as_float((ti << 23) + 0x3F800000u);
    float p = 1.33335581e-3f;
    p = fmaf(p, f, 9.61812911e-3f);
    p = fmaf(p, f, 5.55041087e-2f);
    p = fmaf(p, f, 2.40226507e-1f);
    p = fmaf(p, f, 6.93147181e-1f);
    p = fmaf(p, f, 1.0f);
    return p * s;
}

// ------------------------- merged fp32 -> bf16 hi/lo split --------------------
#define CN1 (ROWS * D_ / 4)
#define CN2 (3 * D_ * D_ / 4)
#define CN3 (D_ * D_ / 4)
__global__ void convert_all(const float4* __restrict__ x,
                            const float4* __restrict__ w_in,
                            const float4* __restrict__ w_out) {
    int i = blockIdx.x * blockDim.x + threadIdx.x;
    const float4* src;
    __nv_bfloat162 *hi, *lo;
    int off;
    if (i < CN1) {
        src = x; hi = (__nv_bfloat162*)g_xhi; lo = (__nv_bfloat162*)g_xlo; off = i;
    } else if (i < CN1 + CN2) {
        src = w_in; hi = (__nv_bfloat162*)g_winhi; lo = (__nv_bfloat162*)g_winlo; off = i - CN1;
    } else if (i < CN1 + CN2 + CN3) {
        src = w_out; hi = (__nv_bfloat162*)g_wouthi; lo = (__nv_bfloat162*)g_woutlo;
        off = i - CN1 - CN2;
    } else return;
    float4 v = src[off];
    __nv_bfloat16 hx, hy, hz, hw, lx, ly, lz, lw;
    split_bf16(v.x, hx, lx); split_bf16(v.y, hy, ly);
    split_bf16(v.z, hz, lz); split_bf16(v.w, hw, lw);
    hi[2*off]   = __halves2bfloat162(hx, hy);
    hi[2*off+1] = __halves2bfloat162(hz, hw);
    lo[2*off]   = __halves2bfloat162(lx, ly);
    lo[2*off+1] = __halves2bfloat162(lz, lw);
}

// ========================= pipelined bf16x3 GEMM (64x128 tile) ================
// C[m,n] = sum_k A[rowmap? rowmap[m]:m, k] * W[n,k] (+bias), K=256, BK=32.
// 8 warps as 2(m) x 4(n); warp tile 32x32; 2-stage cp.async; 61 KB smem.
#define GKP 80
#define ST_A_HI 0
#define ST_A_LO 5120
#define ST_B_HI 10240
#define ST_B_LO 20480
#define ST_SIZE 30720
#define SMEM_GM (2 * ST_SIZE)                    // 61440 B

__global__ __launch_bounds__(256) void gemm_bf16(
    const __nv_bfloat16* __restrict__ Ahi, const __nv_bfloat16* __restrict__ Alo,
    const int* __restrict__ rowmap,
    const __nv_bfloat16* __restrict__ Bhi, const __nv_bfloat16* __restrict__ Blo,
    const float* __restrict__ bias, int M, int N, int mode, float scale,
    float* __restrict__ Cf, __nv_bfloat16* __restrict__ Chi, __nv_bfloat16* __restrict__ Clo,
    __nv_bfloat16* __restrict__ VThi, __nv_bfloat16* __restrict__ VTlo) {
    extern __shared__ char smem[];
    uint32_t sb = smem_u32(smem);
    int tid = threadIdx.x, wid = tid >> 5, lane = tid & 31;
    int rowBase = blockIdx.y * 64, colBase = blockIdx.x * 128;
    int warp_m = (wid >> 2) * 32;                // 0 | 32
    int warp_n = (wid & 3) * 32;                 // 0,32,64,96

    // ---- loaders: A 1 chunk/thread/array, B 2 chunks/thread/array ----
    int ra = tid >> 2, ca = tid & 3;             // A row 0..63, chunk 0..3
    int rb = tid >> 1, cb = (tid & 1) * 2;       // B row 0..127, chunks {cb, cb+1}
    int gar = (rowBase + ra < M) ? (rowmap ? rowmap[rowBase + ra] : rowBase + ra) : 0;
    const __nv_bfloat16* sAh = Ahi + (size_t)gar * KD + ca * 8;
    const __nv_bfloat16* sAl = Alo + (size_t)gar * KD + ca * 8;
    const __nv_bfloat16* sBh = Bhi + (size_t)(colBase + rb) * KD + cb * 8;
    const __nv_bfloat16* sBl = Blo + (size_t)(colBase + rb) * KD + cb * 8;
    uint32_t da = sb + (uint32_t)(ra * GKP + ca * 16);
    uint32_t db = sb + (uint32_t)(rb * GKP + cb * 16);

    auto issue = [&](int kt, int st) {
        uint32_t so = (uint32_t)st * ST_SIZE;
        int ko = kt * 32;
        CP16(da + so + ST_A_HI, sAh + ko);
        CP16(da + so + ST_A_LO, sAl + ko);
        CP16(db + so + ST_B_HI, sBh + ko);  CP16(db + so + ST_B_HI + 16, sBh + ko + 8);
        CP16(db + so + ST_B_LO, sBl + ko);  CP16(db + so + ST_B_LO + 16, sBl + ko + 8);
        CP_COMMIT();
    };

    uint32_t arel[2];
    #pragma unroll
    for (int mf = 0; mf < 2; mf++)
        arel[mf] = (uint32_t)((warp_m + mf * 16 + (lane & 15)) * GKP + (lane >> 4) * 16);
    int bg = lane >> 3, br = lane & 7;
    uint32_t brel0 = (uint32_t)((warp_n + (bg >> 1) * 8 + br) * GKP + (bg & 1) * 16);
    uint32_t brel1 = brel0 + 16 * GKP;

    float acc[2][4][4] = {};

    issue(0, 0);
    #pragma unroll 1
    for (int kt = 0; kt < 8; kt++) {
        int st = kt & 1;
        if (kt + 1 < 8) { issue(kt + 1, (kt + 1) & 1); CP_WAIT(1); }
        else            { CP_WAIT(0); }
        __syncthreads();
        uint32_t base = sb + (uint32_t)st * ST_SIZE;
        #pragma unroll
        for (int kc = 0; kc < 2; kc++) {
            uint32_t koff = (uint32_t)kc * 32;
            uint32_t bh[4][2], bl[4][2];
            ldsm_x4(bh[0][0], bh[0][1], bh[1][0], bh[1][1], base + ST_B_HI + brel0 + koff);
            ldsm_x4(bh[2][0], bh[2][1], bh[3][0], bh[3][1], base + ST_B_HI + brel1 + koff);
            ldsm_x4(bl[0][0], bl[0][1], bl[1][0], bl[1][1], base + ST_B_LO + brel0 + koff);
            ldsm_x4(bl[2][0], bl[2][1], bl[3][0], bl[3][1], base + ST_B_LO + brel1 + koff);
            #pragma unroll
            for (int mf = 0; mf < 2; mf++) {
                uint32_t ah[4], al[4];
                ldsm_x4(ah[0], ah[1], ah[2], ah[3], base + ST_A_HI + arel[mf] + koff);
                ldsm_x4(al[0], al[1], al[2], al[3], base + ST_A_LO + arel[mf] + koff);
                #pragma unroll
                for (int nf = 0; nf < 4; nf++) {
                    mma_bf16(acc[mf][nf], ah, bh[nf]);
                    mma_bf16(acc[mf][nf], ah, bl[nf]);
                    mma_bf16(acc[mf][nf], al, bh[nf]);
                }
            }
        }
        __syncthreads();
    }

    #pragma unroll
    for (int mf = 0; mf < 2; mf++) {
        #pragma unroll
        for (int nf = 0; nf < 4; nf++) {
            int n = colBase + warp_n + nf * 8 + (lane & 3) * 2;
            float b0 = __ldg(bias + n), b1 = __ldg(bias + n + 1);
            #pragma unroll
            for (int half = 0; half < 2; half++) {
                int m = rowBase + warp_m + mf * 16 + (lane >> 2) + half * 8;
                if (m >= M) continue;
                float o0 = acc[mf][nf][half * 2 + 0] + b0;
                float o1 = acc[mf][nf][half * 2 + 1] + b1;
                if (mode == 0) {
                    *(float2*)(Cf + (size_t)m * N + n) = make_float2(o0, o1);
                } else if (mode == 1) {
                    o0 *= scale; o1 *= scale;
                    __nv_bfloat16 h0, l0, h1, l1;
                    split_bf16(o0, h0, l0); split_bf16(o1, h1, l1);
                    *(__nv_bfloat162*)(Chi + (size_t)m * N + n) = __halves2bfloat162(h0, h1);
                    *(__nv_bfloat162*)(Clo + (size_t)m * N + n) = __halves2bfloat162(l0, l1);
                } else {
                    __nv_bfloat16 h0, l0, h1, l1;
                    split_bf16(o0, h0, l0); split_bf16(o1, h1, l1);
                    if (n < 256) {
                        *(__nv_bfloat162*)(Chi + (size_t)m * 256 + n) = __halves2bfloat162(h0, h1);
                        *(__nv_bfloat162*)(Clo + (size_t)m * 256 + n) = __halves2bfloat162(l0, l1);
                    } else {
                        int bb = m / KEEP, j = m - bb * KEEP;
                        int hh = (n - 256) >> 5, dd = (n - 256) & 31;
                        size_t i0 = ((size_t)(bb * H_ + hh) * HD_ + dd) * KPAD + j;
                        size_t i1 = ((size_t)(bb * H_ + hh) * HD_ + dd + 1) * KPAD + j;
                        VThi[i0] = h0; VTlo[i0] = l0;
                        VThi[i1] = h1; VTlo[i1] = l1;
                    }
                }
            }
        }
    }
}

// ========================= MMA attention (register softmax) ==================
#define AQS 80
#define PVS 432
#define A_KHI  0
#define A_KLO  (A_KHI + KPAD * AQS)
#define A_QHI  (A_KLO + KPAD * AQS)
#define A_QLO  (A_QHI + 64 * AQS)
#define A_VTHI (A_QLO + 64 * AQS)
#define A_VTLO (A_VTHI + HD_ * PVS)
#define SMEM_AT (A_VTLO + HD_ * PVS)      // 71168

__global__ __launch_bounds__(128) void attn_mma() {
    extern __shared__ char smem[];
    uint32_t sb = smem_u32(smem);
    int tid = threadIdx.x, wid = tid >> 5, lane = tid & 31;
    int bh_ = blockIdx.x;
    int b = bh_ >> 3, h = bh_ & 7;
    int qbase = blockIdx.y * 64;

    for (int i = tid; i < KPAD * 4; i += 128) {
        int j = i >> 2, c = i & 3;
        uint4 vh = make_uint4(0, 0, 0, 0), vl = vh;
        if (j < KEEP) {
            size_t off = (size_t)(b * KEEP + j) * D_ + h * HD_ + c * 8;
            vh = *(const uint4*)(g_khi + off);
            vl = *(const uint4*)(g_klo + off);
        }
        *(uint4*)(smem + A_KHI + j * AQS + c * 16) = vh;
        *(uint4*)(smem + A_KLO + j * AQS + c * 16) = vl;
    }
    for (int i = tid; i < 64 * 4; i += 128) {
        int r = i >> 2, c = i & 3;
        size_t off = (size_t)(b * S_ + qbase + r) * D_ + h * HD_ + c * 8;
        *(uint4*)(smem + A_QHI + r * AQS + c * 16) = *(const uint4*)(g_qhi + off);
        *(uint4*)(smem + A_QLO + r * AQS + c * 16) = *(const uint4*)(g_qlo + off);
    }
    for (int i = tid; i < HD_ * 26; i += 128) {
        int d = i / 26, c = i % 26;
        size_t off = ((size_t)(b * H_ + h) * HD_ + d) * KPAD + c * 8;
        if (c < 25) {
            *(uint4*)(smem + A_VTHI + d * PVS + c * 16) = *(const uint4*)(g_vthi + off);
            *(uint4*)(smem + A_VTLO + d * PVS + c * 16) = *(const uint4*)(g_vtlo + off);
        } else {
            uint2 vh = *(const uint2*)(g_vthi + off);
            uint2 vl = *(const uint2*)(g_vtlo + off);
            *(uint4*)(smem + A_VTHI + d * PVS + c * 16) = make_uint4(vh.x, vh.y, 0, 0);
            *(uint4*)(smem + A_VTLO + d * PVS + c * 16) = make_uint4(vl.x, vl.y, 0, 0);
        }
    }
    __syncthreads();

    int warp_m = wid * 16;
    int bg = lane >> 3, br = lane & 7;

    uint32_t aqh[2][4], aql[2][4];
    {
        uint32_t ar = (uint32_t)((warp_m + (lane & 15)) * AQS + (lane >> 4) * 16);
        #pragma unroll
        for (int ks = 0; ks < 2; ks++) {
            ldsm_x4(aqh[ks][0], aqh[ks][1], aqh[ks][2], aqh[ks][3], sb + A_QHI + ar + ks * 32);
            ldsm_x4(aql[ks][0], aql[ks][1], aql[ks][2], aql[ks][3], sb + A_QLO + ar + ks * 32);
        }
    }
    float sacc[26][4];
    #pragma unroll
    for (int t = 0; t < 26; t++)
        #pragma unroll
        for (int j = 0; j < 4; j++) sacc[t][j] = 0.f;

    #pragma unroll
    for (int nc = 0; nc < 13; nc++) {
        uint32_t brel = (uint32_t)((nc * 16 + (bg >> 1) * 8 + br) * AQS + (bg & 1) * 16);
        #pragma unroll
        for (int ks = 0; ks < 2; ks++) {
            uint32_t bh[2][2], bl[2][2];
            ldsm_x4(bh[0][0], bh[0][1], bh[1][0], bh[1][1], sb + A_KHI + brel + ks * 32);
            ldsm_x4(bl[0][0], bl[0][1], bl[1][0], bl[1][1], sb + A_KLO + brel + ks * 32);
            #pragma unroll
            for (int nf = 0; nf < 2; nf++) {
                mma_bf16(sacc[nc * 2 + nf], aqh[ks], bh[nf]);
                mma_bf16(sacc[nc * 2 + nf], aql[ks], bh[nf]);
                mma_bf16(sacc[nc * 2 + nf], aqh[ks], bl[nf]);
            }
        }
    }

    if ((lane & 3) >= 2) {
        sacc[25][0] = -1e30f; sacc[25][1] = -1e30f;
        sacc[25][2] = -1e30f; sacc[25][3] = -1e30f;
    }

    float mx0 = -1e30f, mx1 = -1e30f;
    #pragma unroll
    for (int t = 0; t < 26; t++) {
        mx0 = fmaxf(mx0, fmaxf(sacc[t][0], sacc[t][1]));
        mx1 = fmaxf(mx1, fmaxf(sacc[t][2], sacc[t][3]));
    }
    mx0 = fmaxf(mx0, __shfl_xor_sync(0xffffffffu, mx0, 1));
    mx0 = fmaxf(mx0, __shfl_xor_sync(0xffffffffu, mx0, 2));
    mx1 = fmaxf(mx1, __shfl_xor_sync(0xffffffffu, mx1, 1));
    mx1 = fmaxf(mx1, __shfl_xor_sync(0xffffffffu, mx1, 2));
    float sum0 = 0.f, sum1 = 0.f;
    #pragma unroll
    for (int t = 0; t < 26; t++) {
        sacc[t][0] = exp2_fast(sacc[t][0] - mx0); sum0 += sacc[t][0];
        sacc[t][1] = exp2_fast(sacc[t][1] - mx0); sum0 += sacc[t][1];
        sacc[t][2] = exp2_fast(sacc[t][2] - mx1); sum1 += sacc[t][2];
        sacc[t][3] = exp2_fast(sacc[t][3] - mx1); sum1 += sacc[t][3];
    }
    sum0 += __shfl_xor_sync(0xffffffffu, sum0, 1);
    sum0 += __shfl_xor_sync(0xffffffffu, sum0, 2);
    sum1 += __shfl_xor_sync(0xffffffffu, sum1, 1);
    sum1 += __shfl_xor_sync(0xffffffffu, sum1, 2);
    float inv0 = 1.f / sum0, inv1 = 1.f / sum1;

    float oacc[4][4] = {};
    uint32_t br0 = (uint32_t)(((bg >> 1) * 8 + br) * PVS + (bg & 1) * 16);
    uint32_t br1 = br0 + 16 * PVS;
    #pragma unroll
    for (int ks = 0; ks < 13; ks++) {
        uint32_t ph[4], pl[4];
        pack_hi_lo(sacc[2*ks][0],   sacc[2*ks][1],   ph[0], pl[0]);
        pack_hi_lo(sacc[2*ks][2],   sacc[2*ks][3],   ph[1], pl[1]);
        pack_hi_lo(sacc[2*ks+1][0], sacc[2*ks+1][1], ph[2], pl[2]);
        pack_hi_lo(sacc[2*ks+1][2], sacc[2*ks+1][3], ph[3], pl[3]);
        uint32_t koff = (uint32_t)ks * 32;
        uint32_t vh[4][2], vl[4][2];
        ldsm_x4(vh[0][0], vh[0][1], vh[1][0], vh[1][1], sb + A_VTHI + br0 + koff);
        ldsm_x4(vh[2][0], vh[2][1], vh[3][0], vh[3][1], sb + A_VTHI + br1 + koff);
        ldsm_x4(vl[0][0], vl[0][1], vl[1][0], vl[1][1], sb + A_VTLO + br0 + koff);
        ldsm_x4(vl[2][0], vl[2][1], vl[3][0], vl[3][1], sb + A_VTLO + br1 + koff);
        #pragma unroll
        for (int nf = 0; nf < 4; nf++) {
            mma_bf16(oacc[nf], ph, vh[nf]);
            mma_bf16(oacc[nf], pl, vh[nf]);
            mma_bf16(oacc[nf], ph, vl[nf]);
        }
    }

    #pragma unroll
    for (int nf = 0; nf < 4; nf++) {
        int col = h * HD_ + nf * 8 + (lane & 3) * 2;
        #pragma unroll
        for (int half = 0; half < 2; half++) {
            int row = warp_m + (lane >> 2) + half * 8;
            float il = half ? inv1 : inv0;
            float o0 = oacc[nf][half * 2 + 0] * il;
            float o1 = oacc[nf][half * 2 + 1] * il;
            __nv_bfloat16 h0, l0, h1, l1;
            split_bf16(o0, h0, l0); split_bf16(o1, h1, l1);
            size_t m = (size_t)(b * S_ + qbase + row) * D_ + col;
            *(__nv_bfloat162*)(g_athi + m) = __halves2bfloat162(h0, h1);
            *(__nv_bfloat162*)(g_atlo + m) = __halves2bfloat162(l0, l1);
        }
    }
}

// ------------------------- gate GEMM + fused relu/dot/sigmoid ----------------
__global__ __launch_bounds__(256) void gate_gemm(
    const float* __restrict__ A, const float* __restrict__ W,
    const float* __restrict__ bias,
    const float* __restrict__ w2, const float* __restrict__ b2) {
    __shared__ float As[16][68];
    __shared__ float Ws[16][68];
    int tid = threadIdx.x;
    int rowBase = blockIdx.x * 64;
    int ar = tid & 63, ac = (tid >> 6) * 4;
    const float* asrc = A + (size_t)(rowBase + ar) * KD + ac;
    const float* wsrc = W + (size_t)ar * KD + ac;
    float4 a0 = *(const float4*)asrc;
    float4 w0 = *(const float4*)wsrc;
    int tx = tid & 15, ty = tid >> 4;
    float acc[4][4] = {};
    for (int k0 = 0; k0 < KD; k0 += 16) {
        As[ac+0][ar]=a0.x; As[ac+1][ar]=a0.y; As[ac+2][ar]=a0.z; As[ac+3][ar]=a0.w;
        Ws[ac+0][ar]=w0.x; Ws[ac+1][ar]=w0.y; Ws[ac+2][ar]=w0.z; Ws[ac+3][ar]=w0.w;
        __syncthreads();
        if (k0 + 16 < KD) {
            a0 = *(const float4*)(asrc + k0 + 16);
            w0 = *(const float4*)(wsrc + k0 + 16);
        }
        #pragma unroll
        for (int kk = 0; kk < 16; kk++) {
            float a[4], w[4];
            *(float4*)a = *(const float4*)&As[kk][ty * 4];
            *(float4*)w = *(const float4*)&Ws[kk][tx * 4];
            #pragma unroll
            for (int i = 0; i < 4; i++)
                #pragma unroll
                for (int j = 0; j < 4; j++)
                    acc[i][j] = fmaf(a[i], w[j], acc[i][j]);
        }
        __syncthreads();
    }
    float b1v[4], w2v[4];
    #pragma unroll
    for (int j = 0; j < 4; j++) {
        b1v[j] = bias[tx * 4 + j];
        w2v[j] = w2[tx * 4 + j];
    }
    float bb2 = b2[0];
    #pragma unroll
    for (int i = 0; i < 4; i++) {
        float part = 0.f;
        #pragma unroll
        for (int j = 0; j < 4; j++)
            part += fmaxf(acc[i][j] + b1v[j], 0.f) * w2v[j];
        part += __shfl_xor_sync(0xffffffffu, part, 1);
        part += __shfl_xor_sync(0xffffffffu, part, 2);
        part += __shfl_xor_sync(0xffffffffu, part, 4);
        part += __shfl_xor_sync(0xffffffffu, part, 8);
        if (tx == 0)
            g_importance[rowBase + ty * 4 + i] = 1.f / (1.f + expf(-(part + bb2)));
    }
}

// ------------------------- radix-select top-k ---------------------------------
__global__ __launch_bounds__(256) void topk_radix() {
    __shared__ uint32_t bits[S_];
    __shared__ int hist[256];
    __shared__ int s_bin, s_acc;
    __shared__ int cnt_gt, eqn;
    __shared__ int eqlist[256];
    int b = blockIdx.x, t = threadIdx.x;
    for (int i = t; i < S_; i += 256)
        bits[i] = __float_as_uint(g_importance[b * S_ + i]);
    __syncthreads();

    uint32_t prefix = 0, prefmask = 0;
    int k_rem = KEEP;
    #pragma unroll
    for (int lev = 0; lev < 4; lev++) {
        int shift = 24 - lev * 8;
        if (t < 256) hist[t] = 0;
        __syncthreads();
        for (int i = t; i < S_; i += 256) {
            uint32_t v = bits[i];
            if ((v & prefmask) == prefix) atomicAdd(&hist[(v >> shift) & 255], 1);
        }
        __syncthreads();
        if (t == 0) {
            int acc = 0, bin = 255;
            for (; bin > 0; bin--) {
                if (acc + hist[bin] >= k_rem) break;
                acc += hist[bin];
            }
            s_bin = bin; s_acc = acc;
        }
        __syncthreads();
        prefix |= ((uint32_t)s_bin) << shift;
        prefmask |= (0xFFu << shift);
        k_rem -= s_acc;
        __syncthreads();
    }
    if (t == 0) { cnt_gt = 0; eqn = 0; }
    __syncthreads();
    for (int i = t; i < S_; i += 256) {
        uint32_t v = bits[i];
        if (v > prefix) {
            int s = atomicAdd(&cnt_gt, 1);
            g_rowmap[b * KEEP + s] = b * S_ + i;
        } else if (v == prefix) {
            int s = atomicAdd(&eqn, 1);
            if (s < 256) eqlist[s] = i;
        }
    }
    __syncthreads();
    int ne = min(eqn, 256);
    if (t < ne) {
        int idx = eqlist[t], rank = 0;
        for (int j = 0; j < ne; j++) rank += (eqlist[j] < idx);
        if (rank < k_rem) g_rowmap[b * KEEP + cnt_gt + rank] = b * S_ + idx;
    }
}

// ------------------------- host launch ---------------------------------------
extern "C" void kernel_launch(void* const* d_in, const int* in_sizes, int n_in,
                              void* d_out, int out_size) {
    const float* x       = (const float*)d_in[0];
    const float* w_in    = (const float*)d_in[1];
    const float* b_in    = (const float*)d_in[2];
    const float* w_out   = (const float*)d_in[3];
    const float* b_out   = (const float*)d_in[4];
    const float* gate_w1 = (const float*)d_in[5];
    const float* gate_b1 = (const float*)d_in[6];
    const float* gate_w2 = (const float*)d_in[7];
    const float* gate_b2 = (const float*)d_in[8];
    float* out = (float*)d_out;

    void *pRowmap;
    void *pXhi, *pXlo, *pWinhi, *pWinlo, *pWouthi, *pWoutlo;
    void *pQhi, *pQlo, *pKhi, *pKlo, *pVthi, *pVtlo, *pAthi, *pAtlo;
    cudaGetSymbolAddress(&pRowmap, g_rowmap);
    cudaGetSymbolAddress(&pXhi, g_xhi);     cudaGetSymbolAddress(&pXlo, g_xlo);
    cudaGetSymbolAddress(&pWinhi, g_winhi); cudaGetSymbolAddress(&pWinlo, g_winlo);
    cudaGetSymbolAddress(&pWouthi, g_wouthi); cudaGetSymbolAddress(&pWoutlo, g_woutlo);
    cudaGetSymbolAddress(&pQhi, g_qhi);     cudaGetSymbolAddress(&pQlo, g_qlo);
    cudaGetSymbolAddress(&pKhi, g_khi);     cudaGetSymbolAddress(&pKlo, g_klo);
    cudaGetSymbolAddress(&pVthi, g_vthi);   cudaGetSymbolAddress(&pVtlo, g_vtlo);
    cudaGetSymbolAddress(&pAthi, g_athi);   cudaGetSymbolAddress(&pAtlo, g_atlo);

    cudaFuncSetAttribute(gemm_bf16, cudaFuncAttributeMaxDynamicSharedMemorySize, SMEM_GM);
    cudaFuncSetAttribute(attn_mma, cudaFuncAttributeMaxDynamicSharedMemorySize, SMEM_AT);

    // 1. gate (exact fp32, fused relu/dot/sigmoid) -> importance
    gate_gemm<<<ROWS / 64, 256>>>(x, gate_w1, gate_b1, gate_w2, gate_b2);

    // 2. radix-select top-k -> rowmap
    topk_radix<<<B_, 256>>>();

    // 3. merged operand splits
    convert_all<<<(CN1 + CN2 + CN3 + 255) / 256, 256>>>(
        (const float4*)x, (const float4*)w_in, (const float4*)w_out);

    // scale = log2(e) / sqrt(32): scores in log2 domain
    const float scale = 1.4426950408889634f * 0.17677669529663687f;

    // 4. Q = (x @ Wq^T + bq) * scale -> bf16 hi/lo
    gemm_bf16<<<dim3(D_ / 128, ROWS / 64), 256, SMEM_GM>>>(
        (const __nv_bfloat16*)pXhi, (const __nv_bfloat16*)pXlo, nullptr,
        (const __nv_bfloat16*)pWinhi, (const __nv_bfloat16*)pWinlo,
        b_in, ROWS, D_, 1, scale,
        nullptr, (__nv_bfloat16*)pQhi, (__nv_bfloat16*)pQlo, nullptr, nullptr);

    // 5. K,V at kept rows -> K rows + V^T, bf16 hi/lo
    gemm_bf16<<<dim3((2 * D_) / 128, (KV_ROWS + 63) / 64), 256, SMEM_GM>>>(
        (const __nv_bfloat16*)pXhi, (const __nv_bfloat16*)pXlo, (const int*)pRowmap,
        (const __nv_bfloat16*)pWinhi + D_ * D_, (const __nv_bfloat16*)pWinlo + D_ * D_,
        b_in + D_, KV_ROWS, 2 * D_, 2, 1.f,
        nullptr, (__nv_bfloat16*)pKhi, (__nv_bfloat16*)pKlo,
        (__nv_bfloat16*)pVthi, (__nv_bfloat16*)pVtlo);

    // 6. attention (register softmax, FMA-pipe exp)
    attn_mma<<<dim3(B_ * H_, S_ / 64), 128, SMEM_AT>>>();

    // 7. out projection (fp32 out)
    gemm_bf16<<<dim3(D_ / 128, ROWS / 64), 256, SMEM_GM>>>(
        (const __nv_bfloat16*)pAthi, (const __nv_bfloat16*)pAtlo, nullptr,
        (const __nv_bfloat16*)pWouthi, (const __nv_bfloat16*)pWoutlo,
        b_out, ROWS, D_, 0, 1.f,
        out, nullptr, nullptr, nullptr, nullptr);
}

// round 10
// speedup vs baseline: 1.1424x; 1.0168x over previous
#include <cuda_runtime.h>
#include <cuda_bf16.h>
#include <math_constants.h>
#include <cstdint>

#define B_   4
#define S_   2048
#define D_   256
#define H_   8
#define HD_  32
#define KEEP 204            // int(2048 * 0.1)
#define KPAD 208            // padded keys (13 x 16)
#define ROWS (B_ * S_)      // 8192
#define KV_ROWS (B_ * KEEP) // 816
#define KD   256

// ------------------------- scratch (static device globals) -------------------
__device__ float g_importance[ROWS];
__device__ int   g_rowmap[KV_ROWS];
__device__ __nv_bfloat16 g_xhi[ROWS * D_],   g_xlo[ROWS * D_];
__device__ __nv_bfloat16 g_winhi[3 * D_ * D_], g_winlo[3 * D_ * D_];
__device__ __nv_bfloat16 g_wouthi[D_ * D_],  g_woutlo[D_ * D_];
__device__ __nv_bfloat16 g_qhi[ROWS * D_],   g_qlo[ROWS * D_];      // Q * log2e/sqrt(hd)
__device__ __nv_bfloat16 g_khi[KV_ROWS * D_], g_klo[KV_ROWS * D_];
__device__ __nv_bfloat16 g_vthi[B_ * H_ * HD_ * KPAD], g_vtlo[B_ * H_ * HD_ * KPAD];
__device__ __nv_bfloat16 g_athi[ROWS * D_],  g_atlo[ROWS * D_];

// ========================= helpers ============================================
__device__ __forceinline__ uint32_t smem_u32(const void* p) {
    uint32_t a;
    asm("{ .reg .u64 t; cvta.to.shared.u64 t, %1; cvt.u32.u64 %0, t; }" : "=r"(a) : "l"(p));
    return a;
}
__device__ __forceinline__ void ldsm_x4(uint32_t& r0, uint32_t& r1, uint32_t& r2,
                                        uint32_t& r3, uint32_t addr) {
    asm volatile("ldmatrix.sync.aligned.m8n8.x4.shared.b16 {%0,%1,%2,%3}, [%4];"
                 : "=r"(r0), "=r"(r1), "=r"(r2), "=r"(r3) : "r"(addr));
}
__device__ __forceinline__ void mma_bf16(float* c, const uint32_t* a, const uint32_t* b) {
    asm volatile("mma.sync.aligned.m16n8k16.row.col.f32.bf16.bf16.f32 "
                 "{%0,%1,%2,%3}, {%4,%5,%6,%7}, {%8,%9}, {%0,%1,%2,%3};"
                 : "+f"(c[0]), "+f"(c[1]), "+f"(c[2]), "+f"(c[3])
                 : "r"(a[0]), "r"(a[1]), "r"(a[2]), "r"(a[3]), "r"(b[0]), "r"(b[1]));
}
#define CP16(dst, src) \
    asm volatile("cp.async.cg.shared.global [%0], [%1], 16;" :: "r"(dst), "l"(src))
#define CP_COMMIT() asm volatile("cp.async.commit_group;" ::: "memory")
#define CP_WAIT(n)  asm volatile("cp.async.wait_group %0;" :: "n"(n) : "memory")

__device__ __forceinline__ void split_bf16(float v, __nv_bfloat16& h, __nv_bfloat16& l) {
    h = __float2bfloat16(v);
    l = __float2bfloat16(v - __bfloat162float(h));
}
__device__ __forceinline__ void pack_hi_lo(float a, float b, uint32_t& hi, uint32_t& lo) {
    __nv_bfloat16 ha, la, hb, lb;
    split_bf16(a, ha, la); split_bf16(b, hb, lb);
    __nv_bfloat162 th = __halves2bfloat162(ha, hb);
    __nv_bfloat162 tl = __halves2bfloat162(la, lb);
    hi = *(uint32_t*)&th; lo = *(uint32_t*)&tl;
}
// 2^x via FMA pipe (no MUFU): magic rounding + degree-5 poly, rel err < 3e-6
__device__ __forceinline__ float exp2_fast(float x) {
    x = fmaxf(x, -120.f);
    float t = x + 12582912.f;
    float f = x - (t - 12582912.f);
    uint32_t ti = __float_as_uint(t);
    float s = __uint_as_float((ti << 23) + 0x3F800000u);
    float p = 1.33335581e-3f;
    p = fmaf(p, f, 9.61812911e-3f);
    p = fmaf(p, f, 5.55041087e-2f);
    p = fmaf(p, f, 2.40226507e-1f);
    p = fmaf(p, f, 6.93147181e-1f);
    p = fmaf(p, f, 1.0f);
    return p * s;
}

// ========================= bf16x3 GEMM body (64x64 tile, 3-stage) =============
// C[m,n] = sum_k A[rowmap? rowmap[m]:m, k] * W[n,k] (+bias), K=256, BK=32.
// 8 warps as 2(m) x 4(n); warp tile 32x16; single __syncthreads per k-iter.
#define GKP 80
#define G_AHI 0
#define G_ALO 5120
#define G_BHI 10240
#define G_BLO 15360
#define G_STAGE 20480
#define SMEM_GM (3 * G_STAGE)                    // 61440 B

__device__ __forceinline__ void gemm_body(
    int bx, int by, char* smem,
    const __nv_bfloat16* __restrict__ Ahi, const __nv_bfloat16* __restrict__ Alo,
    const int* __restrict__ rowmap,
    const __nv_bfloat16* __restrict__ Bhi, const __nv_bfloat16* __restrict__ Blo,
    const float* __restrict__ bias, int M, int N, int mode, float scale,
    float* __restrict__ Cf, __nv_bfloat16* __restrict__ Chi, __nv_bfloat16* __restrict__ Clo,
    __nv_bfloat16* __restrict__ VThi, __nv_bfloat16* __restrict__ VTlo) {
    uint32_t sb = smem_u32(smem);
    int tid = threadIdx.x, wid = tid >> 5, lane = tid & 31;
    int rowBase = by * 64, colBase = bx * 64;
    int warp_m = (wid >> 2) * 32;                // 0 | 32
    int warp_n = (wid & 3) * 16;                 // 0,16,32,48

    // ---- loaders: 1 16B chunk / thread / array / stage ----
    int ra = tid >> 2, ca = tid & 3;             // row 0..63, chunk 0..3
    int gar = (rowBase + ra < M) ? (rowmap ? rowmap[rowBase + ra] : rowBase + ra) : 0;
    const __nv_bfloat16* sAh = Ahi + (size_t)gar * KD + ca * 8;
    const __nv_bfloat16* sAl = Alo + (size_t)gar * KD + ca * 8;
    const __nv_bfloat16* sBh = Bhi + (size_t)(colBase + ra) * KD + ca * 8;
    const __nv_bfloat16* sBl = Blo + (size_t)(colBase + ra) * KD + ca * 8;
    uint32_t dd = sb + (uint32_t)(ra * GKP + ca * 16);

    auto issue = [&](int kt, int st) {
        uint32_t so = (uint32_t)st * G_STAGE;
        int ko = kt * 32;
        CP16(dd + so + G_AHI, sAh + ko);
        CP16(dd + so + G_ALO, sAl + ko);
        CP16(dd + so + G_BHI, sBh + ko);
        CP16(dd + so + G_BLO, sBl + ko);
        CP_COMMIT();
    };

    uint32_t arel[2];
    #pragma unroll
    for (int mf = 0; mf < 2; mf++)
        arel[mf] = (uint32_t)((warp_m + mf * 16 + (lane & 15)) * GKP + (lane >> 4) * 16);
    int bg = lane >> 3, br = lane & 7;
    uint32_t brel = (uint32_t)((warp_n + (bg >> 1) * 8 + br) * GKP + (bg & 1) * 16);

    float acc[2][2][4] = {};

    issue(0, 0);
    issue(1, 1);
    #pragma unroll 1
    for (int kt = 0; kt < 8; kt++) {
        CP_WAIT(1);
        __syncthreads();
        if (kt < 6) issue(kt + 2, (kt + 2) % 3);
        uint32_t base = sb + (uint32_t)((kt % 3) * G_STAGE);
        #pragma unroll
        for (int kc = 0; kc < 2; kc++) {
            uint32_t koff = (uint32_t)kc * 32;
            uint32_t bh[2][2], bl[2][2];
            ldsm_x4(bh[0][0], bh[0][1], bh[1][0], bh[1][1], base + G_BHI + brel + koff);
            ldsm_x4(bl[0][0], bl[0][1], bl[1][0], bl[1][1], base + G_BLO + brel + koff);
            #pragma unroll
            for (int mf = 0; mf < 2; mf++) {
                uint32_t ah[4], al[4];
                ldsm_x4(ah[0], ah[1], ah[2], ah[3], base + G_AHI + arel[mf] + koff);
                ldsm_x4(al[0], al[1], al[2], al[3], base + G_ALO + arel[mf] + koff);
                #pragma unroll
                for (int nf = 0; nf < 2; nf++) {
                    mma_bf16(acc[mf][nf], ah, bh[nf]);
                    mma_bf16(acc[mf][nf], ah, bl[nf]);
                    mma_bf16(acc[mf][nf], al, bh[nf]);
                }
            }
        }
    }

    #pragma unroll
    for (int mf = 0; mf < 2; mf++) {
        #pragma unroll
        for (int nf = 0; nf < 2; nf++) {
            int n = colBase + warp_n + nf * 8 + (lane & 3) * 2;
            float b0 = __ldg(bias + n), b1 = __ldg(bias + n + 1);
            #pragma unroll
            for (int half = 0; half < 2; half++) {
                int m = rowBase + warp_m + mf * 16 + (lane >> 2) + half * 8;
                if (m >= M) continue;
                float o0 = acc[mf][nf][half * 2 + 0] + b0;
                float o1 = acc[mf][nf][half * 2 + 1] + b1;
                if (mode == 0) {
                    *(float2*)(Cf + (size_t)m * N + n) = make_float2(o0, o1);
                } else if (mode == 1) {
                    o0 *= scale; o1 *= scale;
                    __nv_bfloat16 h0, l0, h1, l1;
                    split_bf16(o0, h0, l0); split_bf16(o1, h1, l1);
                    *(__nv_bfloat162*)(Chi + (size_t)m * N + n) = __halves2bfloat162(h0, h1);
                    *(__nv_bfloat162*)(Clo + (size_t)m * N + n) = __halves2bfloat162(l0, l1);
                } else {
                    __nv_bfloat16 h0, l0, h1, l1;
                    split_bf16(o0, h0, l0); split_bf16(o1, h1, l1);
                    if (n < 256) {
                        *(__nv_bfloat162*)(Chi + (size_t)m * 256 + n) = __halves2bfloat162(h0, h1);
                        *(__nv_bfloat162*)(Clo + (size_t)m * 256 + n) = __halves2bfloat162(l0, l1);
                    } else {
                        int bb = m / KEEP, j = m - bb * KEEP;
                        int hh = (n - 256) >> 5, dd2 = (n - 256) & 31;
                        size_t i0 = ((size_t)(bb * H_ + hh) * HD_ + dd2) * KPAD + j;
                        size_t i1 = ((size_t)(bb * H_ + hh) * HD_ + dd2 + 1) * KPAD + j;
                        VThi[i0] = h0; VTlo[i0] = l0;
                        VThi[i1] = h1; VTlo[i1] = l1;
                    }
                }
            }
        }
    }
}

// ========================= launch 1: gate GEMM || convert ====================
#define CN1 (ROWS * D_ / 4)
#define CN2 (3 * D_ * D_ / 4)
#define CN3 (D_ * D_ / 4)
#define GATE_BLOCKS (ROWS / 64)     // 128
#define CONV_BLOCKS ((CN1 + CN2 + CN3) / 256)   // 2304

__global__ __launch_bounds__(256) void k_gate_convert(
    const float* __restrict__ x, const float* __restrict__ gw1,
    const float* __restrict__ gb1, const float* __restrict__ gw2,
    const float* __restrict__ gb2,
    const float* __restrict__ w_in, const float* __restrict__ w_out) {
    __shared__ float As[16][68];
    __shared__ float Ws[16][68];
    int tid = threadIdx.x;
    if (blockIdx.x >= GATE_BLOCKS) {
        // -------- convert branch --------
        int i = (blockIdx.x - GATE_BLOCKS) * 256 + tid;
        const float4* src;
        __nv_bfloat162 *hi, *lo;
        int off;
        if (i < CN1) {
            src = (const float4*)x; hi = (__nv_bfloat162*)g_xhi; lo = (__nv_bfloat162*)g_xlo; off = i;
        } else if (i < CN1 + CN2) {
            src = (const float4*)w_in; hi = (__nv_bfloat162*)g_winhi; lo = (__nv_bfloat162*)g_winlo;
            off = i - CN1;
        } else {
            src = (const float4*)w_out; hi = (__nv_bfloat162*)g_wouthi; lo = (__nv_bfloat162*)g_woutlo;
            off = i - CN1 - CN2;
        }
        float4 v = src[off];
        __nv_bfloat16 hx, hy, hz, hw, lx, ly, lz, lw;
        split_bf16(v.x, hx, lx); split_bf16(v.y, hy, ly);
        split_bf16(v.z, hz, lz); split_bf16(v.w, hw, lw);
        hi[2*off]   = __halves2bfloat162(hx, hy);
        hi[2*off+1] = __halves2bfloat162(hz, hw);
        lo[2*off]   = __halves2bfloat162(lx, ly);
        lo[2*off+1] = __halves2bfloat162(lz, lw);
        return;
    }
    // -------- gate branch (exact fp32 GEMM + fused relu/dot/sigmoid) --------
    int rowBase = blockIdx.x * 64;
    int ar = tid & 63, ac = (tid >> 6) * 4;
    const float* asrc = x + (size_t)(rowBase + ar) * KD + ac;
    const float* wsrc = gw1 + (size_t)ar * KD + ac;
    float4 a0 = *(const float4*)asrc;
    float4 w0 = *(const float4*)wsrc;
    int tx = tid & 15, ty = tid >> 4;
    float acc[4][4] = {};
    for (int k0 = 0; k0 < KD; k0 += 16) {
        As[ac+0][ar]=a0.x; As[ac+1][ar]=a0.y; As[ac+2][ar]=a0.z; As[ac+3][ar]=a0.w;
        Ws[ac+0][ar]=w0.x; Ws[ac+1][ar]=w0.y; Ws[ac+2][ar]=w0.z; Ws[ac+3][ar]=w0.w;
        __syncthreads();
        if (k0 + 16 < KD) {
            a0 = *(const float4*)(asrc + k0 + 16);
            w0 = *(const float4*)(wsrc + k0 + 16);
        }
        #pragma unroll
        for (int kk = 0; kk < 16; kk++) {
            float a[4], w[4];
            *(float4*)a = *(const float4*)&As[kk][ty * 4];
            *(float4*)w = *(const float4*)&Ws[kk][tx * 4];
            #pragma unroll
            for (int i = 0; i < 4; i++)
                #pragma unroll
                for (int j = 0; j < 4; j++)
                    acc[i][j] = fmaf(a[i], w[j], acc[i][j]);
        }
        __syncthreads();
    }
    float b1v[4], w2v[4];
    #pragma unroll
    for (int j = 0; j < 4; j++) {
        b1v[j] = gb1[tx * 4 + j];
        w2v[j] = gw2[tx * 4 + j];
    }
    float bb2 = gb2[0];
    #pragma unroll
    for (int i = 0; i < 4; i++) {
        float part = 0.f;
        #pragma unroll
        for (int j = 0; j < 4; j++)
            part += fmaxf(acc[i][j] + b1v[j], 0.f) * w2v[j];
        part += __shfl_xor_sync(0xffffffffu, part, 1);
        part += __shfl_xor_sync(0xffffffffu, part, 2);
        part += __shfl_xor_sync(0xffffffffu, part, 4);
        part += __shfl_xor_sync(0xffffffffu, part, 8);
        if (tx == 0)
            g_importance[rowBase + ty * 4 + i] = 1.f / (1.f + expf(-(part + bb2)));
    }
}

// ========================= launch 2: radix top-k || Q GEMM ===================
__device__ void topk_body(int b, char* smem) {
    uint32_t* bits = (uint32_t*)smem;           // 8192 B
    int* hist   = (int*)(smem + 8192);          // 1024 B
    int* eqlist = (int*)(smem + 9216);          // 1024 B
    int* sc     = (int*)(smem + 10240);         // s_bin, s_acc, cnt_gt, eqn
    int t = threadIdx.x;
    for (int i = t; i < S_; i += 256)
        bits[i] = __float_as_uint(g_importance[b * S_ + i]);
    __syncthreads();

    uint32_t prefix = 0, prefmask = 0;
    int k_rem = KEEP;
    #pragma unroll
    for (int lev = 0; lev < 4; lev++) {
        int shift = 24 - lev * 8;
        hist[t] = 0;
        __syncthreads();
        for (int i = t; i < S_; i += 256) {
            uint32_t v = bits[i];
            if ((v & prefmask) == prefix) atomicAdd(&hist[(v >> shift) & 255], 1);
        }
        __syncthreads();
        if (t == 0) {
            int acc = 0, bin = 255;
            for (; bin > 0; bin--) {
                if (acc + hist[bin] >= k_rem) break;
                acc += hist[bin];
            }
            sc[0] = bin; sc[1] = acc;
        }
        __syncthreads();
        prefix |= ((uint32_t)sc[0]) << shift;
        prefmask |= (0xFFu << shift);
        k_rem -= sc[1];
        __syncthreads();
    }
    if (t == 0) { sc[2] = 0; sc[3] = 0; }
    __syncthreads();
    for (int i = t; i < S_; i += 256) {
        uint32_t v = bits[i];
        if (v > prefix) {
            int s = atomicAdd(&sc[2], 1);
            g_rowmap[b * KEEP + s] = b * S_ + i;
        } else if (v == prefix) {
            int s = atomicAdd(&sc[3], 1);
            if (s < 256) eqlist[s] = i;
        }
    }
    __syncthreads();
    int ne = min(sc[3], 256);
    if (t < ne) {
        int idx = eqlist[t], rank = 0;
        for (int j = 0; j < ne; j++) rank += (eqlist[j] < idx);
        if (rank < k_rem) g_rowmap[b * KEEP + sc[2] + rank] = b * S_ + idx;
    }
}

__global__ __launch_bounds__(256) void k_topk_qgemm(
    const float* __restrict__ b_in, float qscale) {
    extern __shared__ char smem[];
    if (blockIdx.x < B_) {
        topk_body(blockIdx.x, smem);
        return;
    }
    int g = blockIdx.x - B_;
    gemm_body(g & 3, g >> 2, smem,
              g_xhi, g_xlo, nullptr, g_winhi, g_winlo,
              b_in, ROWS, D_, 1, qscale,
              nullptr, g_qhi, g_qlo, nullptr, nullptr);
}

// ========================= launch 3: KV GEMM =================================
__global__ __launch_bounds__(256) void k_kvgemm(const float* __restrict__ b_in) {
    extern __shared__ char smem[];
    gemm_body(blockIdx.x, blockIdx.y, smem,
              g_xhi, g_xlo, g_rowmap,
              g_winhi + D_ * D_, g_winlo + D_ * D_,
              b_in + D_, KV_ROWS, 2 * D_, 2, 1.f,
              nullptr, g_khi, g_klo, g_vthi, g_vtlo);
}

// ========================= launch 5: out-proj GEMM ===========================
__global__ __launch_bounds__(256) void k_outgemm(
    const float* __restrict__ b_out, float* __restrict__ out) {
    extern __shared__ char smem[];
    gemm_body(blockIdx.x, blockIdx.y, smem,
              g_athi, g_atlo, nullptr, g_wouthi, g_woutlo,
              b_out, ROWS, D_, 0, 1.f,
              out, nullptr, nullptr, nullptr, nullptr);
}

// ========================= launch 4: MMA attention ===========================
#define AQS 80
#define PVS 432
#define A_KHI  0
#define A_KLO  (A_KHI + KPAD * AQS)
#define A_QHI  (A_KLO + KPAD * AQS)
#define A_QLO  (A_QHI + 64 * AQS)
#define A_VTHI (A_QLO + 64 * AQS)
#define A_VTLO (A_VTHI + HD_ * PVS)
#define SMEM_AT (A_VTLO + HD_ * PVS)      // 71168

__global__ __launch_bounds__(128) void attn_mma() {
    extern __shared__ char smem[];
    uint32_t sb = smem_u32(smem);
    int tid = threadIdx.x, wid = tid >> 5, lane = tid & 31;
    int bh_ = blockIdx.x;
    int b = bh_ >> 3, h = bh_ & 7;
    int qbase = blockIdx.y * 64;

    for (int i = tid; i < KPAD * 4; i += 128) {
        int j = i >> 2, c = i & 3;
        uint4 vh = make_uint4(0, 0, 0, 0), vl = vh;
        if (j < KEEP) {
            size_t off = (size_t)(b * KEEP + j) * D_ + h * HD_ + c * 8;
            vh = *(const uint4*)(g_khi + off);
            vl = *(const uint4*)(g_klo + off);
        }
        *(uint4*)(smem + A_KHI + j * AQS + c * 16) = vh;
        *(uint4*)(smem + A_KLO + j * AQS + c * 16) = vl;
    }
    for (int i = tid; i < 64 * 4; i += 128) {
        int r = i >> 2, c = i & 3;
        size_t off = (size_t)(b * S_ + qbase + r) * D_ + h * HD_ + c * 8;
        *(uint4*)(smem + A_QHI + r * AQS + c * 16) = *(const uint4*)(g_qhi + off);
        *(uint4*)(smem + A_QLO + r * AQS + c * 16) = *(const uint4*)(g_qlo + off);
    }
    for (int i = tid; i < HD_ * 26; i += 128) {
        int d = i / 26, c = i % 26;
        size_t off = ((size_t)(b * H_ + h) * HD_ + d) * KPAD + c * 8;
        if (c < 25) {
            *(uint4*)(smem + A_VTHI + d * PVS + c * 16) = *(const uint4*)(g_vthi + off);
            *(uint4*)(smem + A_VTLO + d * PVS + c * 16) = *(const uint4*)(g_vtlo + off);
        } else {
            uint2 vh = *(const uint2*)(g_vthi + off);
            uint2 vl = *(const uint2*)(g_vtlo + off);
            *(uint4*)(smem + A_VTHI + d * PVS + c * 16) = make_uint4(vh.x, vh.y, 0, 0);
            *(uint4*)(smem + A_VTLO + d * PVS + c * 16) = make_uint4(vl.x, vl.y, 0, 0);
        }
    }
    __syncthreads();

    int warp_m = wid * 16;
    int bg = lane >> 3, br = lane & 7;

    uint32_t aqh[2][4], aql[2][4];
    {
        uint32_t ar = (uint32_t)((warp_m + (lane & 15)) * AQS + (lane >> 4) * 16);
        #pragma unroll
        for (int ks = 0; ks < 2; ks++) {
            ldsm_x4(aqh[ks][0], aqh[ks][1], aqh[ks][2], aqh[ks][3], sb + A_QHI + ar + ks * 32);
            ldsm_x4(aql[ks][0], aql[ks][1], aql[ks][2], aql[ks][3], sb + A_QLO + ar + ks * 32);
        }
    }
    float sacc[26][4];
    #pragma unroll
    for (int t = 0; t < 26; t++)
        #pragma unroll
        for (int j = 0; j < 4; j++) sacc[t][j] = 0.f;

    #pragma unroll
    for (int nc = 0; nc < 13; nc++) {
        uint32_t brel = (uint32_t)((nc * 16 + (bg >> 1) * 8 + br) * AQS + (bg & 1) * 16);
        #pragma unroll
        for (int ks = 0; ks < 2; ks++) {
            uint32_t bh[2][2], bl[2][2];
            ldsm_x4(bh[0][0], bh[0][1], bh[1][0], bh[1][1], sb + A_KHI + brel + ks * 32);
            ldsm_x4(bl[0][0], bl[0][1], bl[1][0], bl[1][1], sb + A_KLO + brel + ks * 32);
            #pragma unroll
            for (int nf = 0; nf < 2; nf++) {
                mma_bf16(sacc[nc * 2 + nf], aqh[ks], bh[nf]);
                mma_bf16(sacc[nc * 2 + nf], aql[ks], bh[nf]);
                mma_bf16(sacc[nc * 2 + nf], aqh[ks], bl[nf]);
            }
        }
    }

    if ((lane & 3) >= 2) {
        sacc[25][0] = -1e30f; sacc[25][1] = -1e30f;
        sacc[25][2] = -1e30f; sacc[25][3] = -1e30f;
    }

    float mx0 = -1e30f, mx1 = -1e30f;
    #pragma unroll
    for (int t = 0; t < 26; t++) {
        mx0 = fmaxf(mx0, fmaxf(sacc[t][0], sacc[t][1]));
        mx1 = fmaxf(mx1, fmaxf(sacc[t][2], sacc[t][3]));
    }
    mx0 = fmaxf(mx0, __shfl_xor_sync(0xffffffffu, mx0, 1));
    mx0 = fmaxf(mx0, __shfl_xor_sync(0xffffffffu, mx0, 2));
    mx1 = fmaxf(mx1, __shfl_xor_sync(0xffffffffu, mx1, 1));
    mx1 = fmaxf(mx1, __shfl_xor_sync(0xffffffffu, mx1, 2));
    float sum0 = 0.f, sum1 = 0.f;
    #pragma unroll
    for (int t = 0; t < 26; t++) {
        sacc[t][0] = exp2_fast(sacc[t][0] - mx0); sum0 += sacc[t][0];
        sacc[t][1] = exp2_fast(sacc[t][1] - mx0); sum0 += sacc[t][1];
        sacc[t][2] = exp2_fast(sacc[t][2] - mx1); sum1 += sacc[t][2];
        sacc[t][3] = exp2_fast(sacc[t][3] - mx1); sum1 += sacc[t][3];
    }
    sum0 += __shfl_xor_sync(0xffffffffu, sum0, 1);
    sum0 += __shfl_xor_sync(0xffffffffu, sum0, 2);
    sum1 += __shfl_xor_sync(0xffffffffu, sum1, 1);
    sum1 += __shfl_xor_sync(0xffffffffu, sum1, 2);
    float inv0 = 1.f / sum0, inv1 = 1.f / sum1;

    float oacc[4][4] = {};
    uint32_t br0 = (uint32_t)(((bg >> 1) * 8 + br) * PVS + (bg & 1) * 16);
    uint32_t br1 = br0 + 16 * PVS;
    #pragma unroll
    for (int ks = 0; ks < 13; ks++) {
        uint32_t ph[4], pl[4];
        pack_hi_lo(sacc[2*ks][0],   sacc[2*ks][1],   ph[0], pl[0]);
        pack_hi_lo(sacc[2*ks][2],   sacc[2*ks][3],   ph[1], pl[1]);
        pack_hi_lo(sacc[2*ks+1][0], sacc[2*ks+1][1], ph[2], pl[2]);
        pack_hi_lo(sacc[2*ks+1][2], sacc[2*ks+1][3], ph[3], pl[3]);
        uint32_t koff = (uint32_t)ks * 32;
        uint32_t vh[4][2], vl[4][2];
        ldsm_x4(vh[0][0], vh[0][1], vh[1][0], vh[1][1], sb + A_VTHI + br0 + koff);
        ldsm_x4(vh[2][0], vh[2][1], vh[3][0], vh[3][1], sb + A_VTHI + br1 + koff);
        ldsm_x4(vl[0][0], vl[0][1], vl[1][0], vl[1][1], sb + A_VTLO + br0 + koff);
        ldsm_x4(vl[2][0], vl[2][1], vl[3][0], vl[3][1], sb + A_VTLO + br1 + koff);
        #pragma unroll
        for (int nf = 0; nf < 4; nf++) {
            mma_bf16(oacc[nf], ph, vh[nf]);
            mma_bf16(oacc[nf], pl, vh[nf]);
            mma_bf16(oacc[nf], ph, vl[nf]);
        }
    }

    #pragma unroll
    for (int nf = 0; nf < 4; nf++) {
        int col = h * HD_ + nf * 8 + (lane & 3) * 2;
        #pragma unroll
        for (int half = 0; half < 2; half++) {
            int row = warp_m + (lane >> 2) + half * 8;
            float il = half ? inv1 : inv0;
            float o0 = oacc[nf][half * 2 + 0] * il;
            float o1 = oacc[nf][half * 2 + 1] * il;
            __nv_bfloat16 h0, l0, h1, l1;
            split_bf16(o0, h0, l0); split_bf16(o1, h1, l1);
            size_t m = (size_t)(b * S_ + qbase + row) * D_ + col;
            *(__nv_bfloat162*)(g_athi + m) = __halves2bfloat162(h0, h1);
            *(__nv_bfloat162*)(g_atlo + m) = __halves2bfloat162(l0, l1);
        }
    }
}

// ------------------------- host launch ---------------------------------------
extern "C" void kernel_launch(void* const* d_in, const int* in_sizes, int n_in,
                              void* d_out, int out_size) {
    const float* x       = (const float*)d_in[0];
    const float* w_in    = (const float*)d_in[1];
    const float* b_in    = (const float*)d_in[2];
    const float* w_out   = (const float*)d_in[3];
    const float* b_out   = (const float*)d_in[4];
    const float* gate_w1 = (const float*)d_in[5];
    const float* gate_b1 = (const float*)d_in[6];
    const float* gate_w2 = (const float*)d_in[7];
    const float* gate_b2 = (const float*)d_in[8];
    float* out = (float*)d_out;

    cudaFuncSetAttribute(k_topk_qgemm, cudaFuncAttributeMaxDynamicSharedMemorySize, SMEM_GM);
    cudaFuncSetAttribute(k_kvgemm, cudaFuncAttributeMaxDynamicSharedMemorySize, SMEM_GM);
    cudaFuncSetAttribute(k_outgemm, cudaFuncAttributeMaxDynamicSharedMemorySize, SMEM_GM);
    cudaFuncSetAttribute(attn_mma, cudaFuncAttributeMaxDynamicSharedMemorySize, SMEM_AT);

    // scale = log2(e) / sqrt(32): scores come out of QK^T in log2 domain
    const float qscale = 1.4426950408889634f * 0.17677669529663687f;

    // 1. gate (exact fp32) || fp32->bf16 hi/lo conversions
    k_gate_convert<<<GATE_BLOCKS + CONV_BLOCKS, 256>>>(
        x, gate_w1, gate_b1, gate_w2, gate_b2, w_in, w_out);

    // 2. radix top-k (4 blocks) || Q projection GEMM (512 blocks)
    k_topk_qgemm<<<B_ + 4 * (ROWS / 64), 256, SMEM_GM>>>(b_in, qscale);

    // 3. K,V at kept rows -> K rows + V^T, bf16 hi/lo
    k_kvgemm<<<dim3((2 * D_) / 64, (KV_ROWS + 63) / 64), 256, SMEM_GM>>>(b_in);

    // 4. attention (register softmax, FMA-pipe exp)
    attn_mma<<<dim3(B_ * H_, S_ / 64), 128, SMEM_AT>>>();

    // 5. out projection (fp32 out)
    k_outgemm<<<dim3(D_ / 64, ROWS / 64), 256, SMEM_GM>>>(b_out, out);
}